// round 17
// baseline (speedup 1.0000x reference)
#include <cuda_runtime.h>
#include <cuda_fp16.h>
#include <cstdint>

// Grouped conv2d via implicit GEMM on mma.sync (HMMA), single-pass fp16.
// x[16,256,128,128] * W[512,16,3,3] (groups=16) + b -> out[16,512,128,128]
// R17 = R16 + (a) ROWS=16 CTAs (halo 18/16, W-copy amortized), (b) warp tile
//   4 rows x 8 px x 32 co: V cells (3/dw) reused across all dh AND both mt.
//   Pre-formatted weights (prep_weights) unchanged.

#define THREADS 512
#define ROWS 16

// ---- smem layout (bytes) ----
#define SWF_OFF   0
#define SWF_BYTES (9 * 1024)                // W frags: 9 taps x 32 lanes x 32B
// x: [row-pair p 0..8][c 0..129][slot 0..3] 16B cells {row-even 8B, row-odd 8B}
#define PSTRIDE   (130 * 64)                // 8320
#define SX_OFF    SWF_BYTES                 // 9216
#define SX_BYTES  (9 * PSTRIDE)             // 74880 (ROWS+2 = 18 staged rows)
#define SBIAS_OFF (SX_OFF + SX_BYTES)       // 84096
#define SMEM_TOTAL (SBIAS_OFF + 128)        // 84224  (x2 CTA = 168KB <= 228KB)

// fragment-formatted weights for all 16 groups (filled by prep_weights)
__device__ uint32_t g_wfrag[16 * 2304];

__device__ __forceinline__ void mma16816(float& c0, float& c1, float& c2, float& c3,
                                         uint32_t a0, uint32_t a1, uint32_t a2, uint32_t a3,
                                         uint32_t b0, uint32_t b1) {
    asm volatile("mma.sync.aligned.m16n8k16.row.col.f32.f16.f16.f32 "
                 "{%0,%1,%2,%3}, {%4,%5,%6,%7}, {%8,%9}, {%0,%1,%2,%3};"
                 : "+f"(c0), "+f"(c1), "+f"(c2), "+f"(c3)
                 : "r"(a0), "r"(a1), "r"(a2), "r"(a3), "r"(b0), "r"(b1));
}

__device__ __forceinline__ uint32_t h2pack(float v0, float v1) {
    __half2 h = __floats2half2_rn(v0, v1);
    return *(uint32_t*)&h;
}

// W-frag swizzle (bit7->bit4, 16B blocks)
__device__ __forceinline__ uint32_t wswz(uint32_t a) {
    return a ^ (((a >> 7) & 1u) << 4);
}
// x cell address: slot rotated by c-quad (conflict-free mainloop LDS.128)
__device__ __forceinline__ uint32_t xaddr(int p, int c, int slot) {
    return (uint32_t)(p * PSTRIDE + c * 64 + ((slot ^ ((c >> 2) & 3)) << 4));
}

// ---- pre-kernel: scatter-gather weights ONCE into fragment layout ----
__global__ void prep_weights(const float* __restrict__ w) {
    const int g = blockIdx.x;
    const float* wgp = w + (size_t)(g * 32) * 144;
    for (int idx = threadIdx.x; idx < 2304; idx += 256) {
        int slot  = idx & 7;
        int lane2 = (idx >> 3) & 31;
        int tap   = idx >> 8;           // 0..8
        int mt = slot >> 2, fi = slot & 3;
        int co  = mt * 16 + (lane2 >> 2) + (fi & 1) * 8;
        int ci0 = 2 * (lane2 & 3) + (fi >> 1) * 8;
        float v0 = wgp[co * 144 + ci0 * 9 + tap];
        float v1 = wgp[co * 144 + (ci0 + 1) * 9 + tap];
        uint32_t lg = (uint32_t)(tap * 1024 + lane2 * 32 + slot * 4);
        g_wfrag[g * 2304 + (wswz(lg) >> 2)] = h2pack(v0, v1);
    }
}

__global__ __launch_bounds__(THREADS, 2)
void grouped_conv_hmma(const float* __restrict__ x,
                       const float* __restrict__ w,
                       const float* __restrict__ bias,
                       float* __restrict__ out)
{
    extern __shared__ char smem[];
    char* swf = smem + SWF_OFF;
    char* sx  = smem + SX_OFF;
    float* sbias = (float*)(smem + SBIAS_OFF);

    const int tid = threadIdx.x;
    const int wid = tid >> 5;
    const int lane = tid & 31;

    const int hb = blockIdx.x;          // 0..7  (16-row blocks)
    const int ng = blockIdx.y;          // 0..255
    const int n  = ng >> 4;
    const int g  = ng & 15;
    const int h0 = hb * ROWS;

    // ---- stage x: 1152 units = (p 0..8, slot 0..3, gw-quad 0..31) ----
    const float* xg = x + (size_t)(n * 256 + g * 16) * 16384;
    #pragma unroll
    for (int it = 0; it < 3; ++it) {
        int su = tid + it * THREADS;
        if (su < 1152) {
            int qd   = su & 31;
            int slot = (su >> 5) & 3;
            int p    = su >> 7;          // 0..8
            int gw0  = qd * 4;
            float v[2][4][4];            // [row][plane e][k]
            #pragma unroll
            for (int rr = 0; rr < 2; ++rr) {
                int gh = h0 - 1 + 2 * p + rr;
                if ((unsigned)gh < 128u) {
                    const float* base = xg + gh * 128 + gw0;
                    *(float4*)v[rr][0] = *(const float4*)(base + (size_t)(2 * slot)     * 16384);
                    *(float4*)v[rr][1] = *(const float4*)(base + (size_t)(2 * slot + 1) * 16384);
                    *(float4*)v[rr][2] = *(const float4*)(base + (size_t)(2 * slot + 8) * 16384);
                    *(float4*)v[rr][3] = *(const float4*)(base + (size_t)(2 * slot + 9) * 16384);
                } else {
                    #pragma unroll
                    for (int e = 0; e < 4; ++e)
                        #pragma unroll
                        for (int k = 0; k < 4; ++k) v[rr][e][k] = 0.0f;
                }
            }
            #pragma unroll
            for (int k = 0; k < 4; ++k) {
                int c = gw0 + 1 + k;
                uint4 cell;
                cell.x = h2pack(v[0][0][k], v[0][1][k]);
                cell.y = h2pack(v[0][2][k], v[0][3][k]);
                cell.z = h2pack(v[1][0][k], v[1][1][k]);
                cell.w = h2pack(v[1][2][k], v[1][3][k]);
                *(uint4*)(sx + xaddr(p, c, slot)) = cell;
            }
        }
    }
    // zero edge cells c=0, c=129 (9 p-cells x 4 slots x 2 edges = 72)
    if (tid < 72) {
        int slot = tid & 3;
        int c    = ((tid >> 2) & 1) ? 129 : 0;
        int p    = tid >> 3;            // 0..8
        uint4 z = make_uint4(0u, 0u, 0u, 0u);
        *(uint4*)(sx + xaddr(p, c, slot)) = z;
    }

    // ---- stage W: coalesced copy of pre-formatted fragments ----
    {
        const uint4* src = (const uint4*)(g_wfrag + g * 2304);
        uint4* dst = (uint4*)swf;
        for (int i = tid; i < 576; i += THREADS) dst[i] = src[i];
    }
    if (tid < 32) sbias[tid] = bias[g * 32 + tid];
    __syncthreads();

    // ---- main: warp = (row group rg: 4 rows, px base pc*32); 4 chunks of 8 px ----
    const int rg = wid >> 2;             // 0..3 : output rows 4rg..4rg+3
    const int pc = wid & 3;              // px base pc*32
    const int l4 = lane >> 2;            // B n-index (pixel) / D m-row
    const int t4 = lane & 3;             // B k-slot / D px-pair

    const uint32_t bswF = wswz((uint32_t)(lane * 32));

    #pragma unroll 1
    for (int chunk = 0; chunk < 4; ++chunk) {
        const int pxb = pc * 32 + chunk * 8;
        float acc[4][2][4];              // [row j][mt][4]
        #pragma unroll
        for (int j = 0; j < 4; ++j)
            #pragma unroll
            for (int m = 0; m < 2; ++m)
                #pragma unroll
                for (int k = 0; k < 4; ++k) acc[j][m][k] = 0.0f;

        #pragma unroll
        for (int dw = 0; dw < 3; ++dw) {
            // V cells: staged row pairs p = 2rg .. 2rg+2 (rows 4rg .. 4rg+5)
            const int c = pxb + dw + l4;
            uint4 V[3];
            #pragma unroll
            for (int jc = 0; jc < 3; ++jc)
                V[jc] = *(const uint4*)(sx + xaddr(2 * rg + jc, c, t4));

            #pragma unroll
            for (int dh = 0; dh < 3; ++dh) {
                const uint32_t bo = (uint32_t)((dh * 3 + dw) * 1024) + bswF;
                uint4 awA = *(const uint4*)(swf + bo);          // mt0
                uint4 awB = *(const uint4*)(swf + (bo ^ 16));   // mt1

                #pragma unroll
                for (int j = 0; j < 4; ++j) {
                    const int sr = j + dh;                      // staged row - 4rg
                    const int cell = sr >> 1;
                    uint32_t b0 = (sr & 1) ? V[cell].z : V[cell].x;
                    uint32_t b1 = (sr & 1) ? V[cell].w : V[cell].y;
                    mma16816(acc[j][0][0], acc[j][0][1], acc[j][0][2], acc[j][0][3],
                             awA.x, awA.y, awA.z, awA.w, b0, b1);
                    mma16816(acc[j][1][0], acc[j][1][1], acc[j][1][2], acc[j][1][3],
                             awB.x, awB.y, awB.z, awB.w, b0, b1);
                }
            }
        }

        // ---- epilogue: rows h0+4rg+j, px pxb+2t4, co mt*16 + l4 (+8) ----
        float* og = out + (size_t)(n * 512 + g * 32) * 16384
                        + (size_t)(h0 + 4 * rg) * 128;
        #pragma unroll
        for (int j = 0; j < 4; ++j) {
            float* ogr = og + j * 128;
            const int px = pxb + 2 * t4;
            #pragma unroll
            for (int mt = 0; mt < 2; ++mt) {
                const float blo = sbias[mt * 16 + l4];
                const float bhi = sbias[mt * 16 + l4 + 8];
                float2 v01, v23;
                v01.x = acc[j][mt][0] + blo;
                v01.y = acc[j][mt][1] + blo;
                v23.x = acc[j][mt][2] + bhi;
                v23.y = acc[j][mt][3] + bhi;
                *(float2*)(ogr + (size_t)(mt * 16 + l4) * 16384 + px)     = v01;
                *(float2*)(ogr + (size_t)(mt * 16 + l4 + 8) * 16384 + px) = v23;
            }
        }
    }
}

extern "C" void kernel_launch(void* const* d_in, const int* in_sizes, int n_in,
                              void* d_out, int out_size)
{
    const float* x = (const float*)d_in[0];
    const float* w = (const float*)d_in[1];
    const float* b = (const float*)d_in[2];
    float* out = (float*)d_out;

    cudaFuncSetAttribute(grouped_conv_hmma,
                         cudaFuncAttributeMaxDynamicSharedMemorySize, SMEM_TOTAL);

    prep_weights<<<16, 256>>>(w);

    dim3 grid(128 / ROWS, 256);   // 16-row h blocks, n*16+g
    grouped_conv_hmma<<<grid, THREADS, SMEM_TOTAL>>>(x, w, b, out);
}